// round 2
// baseline (speedup 1.0000x reference)
#include <cuda_runtime.h>

// image [B=4, C=1, D=128, H=256, W=256] fp32
// out   [B, 2, D, H, W]: ch0 = copy, ch1 = sqrt(Gx^2+Gy^2+Gz^2 + 1e-8)
#define DIM_D 128
#define DIM_H 256
#define DIM_W 256
#define PLANE (DIM_H * DIM_W)
#define DCHUNK 16

__device__ __forceinline__ float4 f4zero() { return make_float4(0.f, 0.f, 0.f, 0.f); }

// Issue raw loads for one plane: 3 rows x (1 float4 + boundary-lane scalars).
__device__ __forceinline__ void load_raw(
    const float* __restrict__ base, int p, bool pvalid,
    const size_t* __restrict__ rowoff, const bool* __restrict__ hv,
    int lane, int w0,
    float4 c[3], float s_l[3], float s_r[3])
{
    const float* pl = base + (size_t)p * PLANE;
#pragma unroll
    for (int r = 0; r < 3; r++) {
        float4 cc = f4zero();
        float xl = 0.f, xr = 0.f;
        if (pvalid && hv[r]) {
            const float* row = pl + rowoff[r];
            cc = __ldg(reinterpret_cast<const float4*>(row));
            if (lane == 0 && w0 > 0)            xl = __ldg(row - 1);
            if (lane == 31 && w0 + 4 < DIM_W)   xr = __ldg(row + 4);
        }
        c[r] = cc; s_l[r] = xl; s_r[r] = xr;
    }
}

// Fold raw plane into separable partials:
//   A = s_h*s_w(x)  (Gz = d_d(A));  B = s_h*d_w(x) (Gx = s_d(B));  C = d_h*s_w(x) (Gy = s_d(C))
__device__ __forceinline__ void make_partials(
    const float4 c[3], const float s_l[3], const float s_r[3], int lane,
    float4& A, float4& B, float4& C, float4& cen)
{
    float4 u[3], v[3];
#pragma unroll
    for (int r = 0; r < 3; r++) {
        float4 cc = c[r];
        float xl = __shfl_up_sync(0xffffffffu, cc.w, 1);
        if (lane == 0)  xl = s_l[r];
        float xr = __shfl_down_sync(0xffffffffu, cc.x, 1);
        if (lane == 31) xr = s_r[r];
        u[r].x = xl   + 2.f * cc.x + cc.y;
        u[r].y = cc.x + 2.f * cc.y + cc.z;
        u[r].z = cc.y + 2.f * cc.z + cc.w;
        u[r].w = cc.z + 2.f * cc.w + xr;
        v[r].x = cc.y - xl;
        v[r].y = cc.z - cc.x;
        v[r].z = cc.w - cc.y;
        v[r].w = xr   - cc.z;
    }
    cen = c[1];
    A.x = u[0].x + 2.f * u[1].x + u[2].x;
    A.y = u[0].y + 2.f * u[1].y + u[2].y;
    A.z = u[0].z + 2.f * u[1].z + u[2].z;
    A.w = u[0].w + 2.f * u[1].w + u[2].w;
    B.x = v[0].x + 2.f * v[1].x + v[2].x;
    B.y = v[0].y + 2.f * v[1].y + v[2].y;
    B.z = v[0].z + 2.f * v[1].z + v[2].z;
    B.w = v[0].w + 2.f * v[1].w + v[2].w;
    C.x = u[2].x - u[0].x;
    C.y = u[2].y - u[0].y;
    C.z = u[2].z - u[0].z;
    C.w = u[2].w - u[0].w;
}

__global__ void __launch_bounds__(256, 3)
sobel_edge_kernel(const float* __restrict__ img, float* __restrict__ out)
{
    const int tx   = threadIdx.x;       // 0..63 -> w columns
    const int ty   = threadIdx.y;       // 0..3  -> h rows
    const int lane = tx & 31;
    const int w0   = tx * 4;
    const int h    = blockIdx.y * 4 + ty;
    const int d0   = blockIdx.x * DCHUNK;
    const int b    = blockIdx.z;

    const float* base = img + (size_t)b * (DIM_D * PLANE);
    float* o0 = out + (size_t)b * 2 * (DIM_D * PLANE) + (size_t)h * DIM_W + w0;
    float* o1 = o0 + (size_t)(DIM_D * PLANE);

    bool hv[3];
    hv[0] = (h - 1) >= 0;
    hv[1] = true;
    hv[2] = (h + 1) < DIM_H;
    size_t rowoff[3];
    rowoff[0] = (size_t)(h - 1) * DIM_W + w0;  // guarded by hv[0]
    rowoff[1] = (size_t)h * DIM_W + w0;
    rowoff[2] = (size_t)(h + 1) * DIM_W + w0;

    float4 A0, B0, C0, A1, B1, C1, A2, B2, C2, cen1, cen2, dummy;
    float4 rc[3]; float rl[3], rr[3];

    // Prologue: partials for planes d0-1 (ring slot 1) and d0 (ring slot 2)
    load_raw(base, d0 - 1, (d0 - 1) >= 0, rowoff, hv, lane, w0, rc, rl, rr);
    make_partials(rc, rl, rr, lane, A1, B1, C1, dummy);
    load_raw(base, d0, true, rowoff, hv, lane, w0, rc, rl, rr);
    make_partials(rc, rl, rr, lane, A2, B2, C2, cen2);

#pragma unroll 1
    for (int dd = 0; dd <= DCHUNK; dd++) {
        const int p = d0 + dd + 1;
        const bool lv = (dd < DCHUNK) && (p < DIM_D);

        // (1) issue next-plane loads (consumed at the end of this iteration)
        load_raw(base, p, lv, rowoff, hv, lane, w0, rc, rl, rr);

        // (2) output plane d = d0+dd-1 from the ring (independent of the loads above)
        if (dd >= 1) {
            const int d = d0 + dd - 1;
            float4 gx, gy, gz, m;
            gx.x = B0.x + 2.f * B1.x + B2.x;
            gx.y = B0.y + 2.f * B1.y + B2.y;
            gx.z = B0.z + 2.f * B1.z + B2.z;
            gx.w = B0.w + 2.f * B1.w + B2.w;
            gy.x = C0.x + 2.f * C1.x + C2.x;
            gy.y = C0.y + 2.f * C1.y + C2.y;
            gy.z = C0.z + 2.f * C1.z + C2.z;
            gy.w = C0.w + 2.f * C1.w + C2.w;
            gz.x = A2.x - A0.x;
            gz.y = A2.y - A0.y;
            gz.z = A2.z - A0.z;
            gz.w = A2.w - A0.w;
            m.x = sqrtf(fmaf(gx.x, gx.x, fmaf(gy.x, gy.x, fmaf(gz.x, gz.x, 1e-8f))));
            m.y = sqrtf(fmaf(gx.y, gx.y, fmaf(gy.y, gy.y, fmaf(gz.y, gz.y, 1e-8f))));
            m.z = sqrtf(fmaf(gx.z, gx.z, fmaf(gy.z, gy.z, fmaf(gz.z, gz.z, 1e-8f))));
            m.w = sqrtf(fmaf(gx.w, gx.w, fmaf(gy.w, gy.w, fmaf(gz.w, gz.w, 1e-8f))));

            const size_t off = (size_t)d * PLANE;
            __stcs(reinterpret_cast<float4*>(o0 + off), cen1);  // copy channel
            __stcs(reinterpret_cast<float4*>(o1 + off), m);     // magnitude channel
        }

        // (3) rotate ring and fold the just-loaded plane into slot 2
        if (dd < DCHUNK) {
            A0 = A1; B0 = B1; C0 = C1;
            A1 = A2; B1 = B2; C1 = C2;
            cen1 = cen2;
            make_partials(rc, rl, rr, lane, A2, B2, C2, cen2);
        }
    }
}

extern "C" void kernel_launch(void* const* d_in, const int* in_sizes, int n_in,
                              void* d_out, int out_size)
{
    const float* img = (const float*)d_in[0];
    float* out = (float*)d_out;

    dim3 block(64, 4, 1);                         // 256 threads
    dim3 grid(DIM_D / DCHUNK, DIM_H / 4, 4);      // 8 x 64 x 4 = 2048 CTAs

    sobel_edge_kernel<<<grid, block>>>(img, out);
}

// round 3
// speedup vs baseline: 1.2536x; 1.2536x over previous
#include <cuda_runtime.h>

// image [B=4, C=1, D=128, H=256, W=256] fp32
// out   [B, 2, D, H, W]: ch0 = copy, ch1 = sqrt(Gx^2+Gy^2+Gz^2 + 1e-8)
#define DIM_D 128
#define DIM_H 256
#define DIM_W 256
#define PLANE (DIM_H * DIM_W)
#define DCHUNK 32

__device__ __forceinline__ float4 f4zero() { return make_float4(0.f, 0.f, 0.f, 0.f); }

// Issue raw loads for one plane: 3 rows x (1 float4 + 2 halo scalars).
// All loads land in registers; caller folds them later (software pipeline).
__device__ __forceinline__ void load_raw(
    const float* __restrict__ base, int p, bool pvalid,
    const size_t* __restrict__ rowoff, const bool* __restrict__ hv,
    int w0,
    float4 c[3], float s_l[3], float s_r[3])
{
    const float* pl = base + (size_t)p * PLANE;
#pragma unroll
    for (int r = 0; r < 3; r++) {
        float4 cc = f4zero();
        float xl = 0.f, xr = 0.f;
        if (pvalid && hv[r]) {
            const float* row = pl + rowoff[r];
            cc = __ldg(reinterpret_cast<const float4*>(row));
            if (w0 > 0)          xl = __ldg(row - 1);
            if (w0 + 4 < DIM_W)  xr = __ldg(row + 4);
        }
        c[r] = cc; s_l[r] = xl; s_r[r] = xr;
    }
}

// Fold raw plane into separable partials:
//   A = s_h*s_w(x)  (Gz = d_d(A));  B = s_h*d_w(x) (Gx = s_d(B));  C = d_h*s_w(x) (Gy = s_d(C))
__device__ __forceinline__ void make_partials(
    const float4 c[3], const float s_l[3], const float s_r[3],
    float4& A, float4& B, float4& C, float4& cen)
{
    float4 u[3], v[3];
#pragma unroll
    for (int r = 0; r < 3; r++) {
        const float4 cc = c[r];
        const float xl = s_l[r];
        const float xr = s_r[r];
        u[r].x = xl   + 2.f * cc.x + cc.y;
        u[r].y = cc.x + 2.f * cc.y + cc.z;
        u[r].z = cc.y + 2.f * cc.z + cc.w;
        u[r].w = cc.z + 2.f * cc.w + xr;
        v[r].x = cc.y - xl;
        v[r].y = cc.z - cc.x;
        v[r].z = cc.w - cc.y;
        v[r].w = xr   - cc.z;
    }
    cen = c[1];
    A.x = u[0].x + 2.f * u[1].x + u[2].x;
    A.y = u[0].y + 2.f * u[1].y + u[2].y;
    A.z = u[0].z + 2.f * u[1].z + u[2].z;
    A.w = u[0].w + 2.f * u[1].w + u[2].w;
    B.x = v[0].x + 2.f * v[1].x + v[2].x;
    B.y = v[0].y + 2.f * v[1].y + v[2].y;
    B.z = v[0].z + 2.f * v[1].z + v[2].z;
    B.w = v[0].w + 2.f * v[1].w + v[2].w;
    C.x = u[2].x - u[0].x;
    C.y = u[2].y - u[0].y;
    C.z = u[2].z - u[0].z;
    C.w = u[2].w - u[0].w;
}

__global__ void __launch_bounds__(256)
sobel_edge_kernel(const float* __restrict__ img, float* __restrict__ out)
{
    const int tx = threadIdx.x;        // 0..63 -> w columns (float4 each)
    const int ty = threadIdx.y;        // 0..3  -> h rows
    const int w0 = tx * 4;
    const int h  = blockIdx.y * 4 + ty;
    const int d0 = blockIdx.x * DCHUNK;
    const int b  = blockIdx.z;

    const float* base = img + (size_t)b * (DIM_D * PLANE);
    float* o0 = out + (size_t)b * 2 * (DIM_D * PLANE) + (size_t)h * DIM_W + w0;
    float* o1 = o0 + (size_t)(DIM_D * PLANE);

    bool hv[3];
    hv[0] = (h - 1) >= 0;
    hv[1] = true;
    hv[2] = (h + 1) < DIM_H;
    size_t rowoff[3];
    rowoff[0] = (size_t)(h - 1) * DIM_W + w0;  // guarded by hv[0]
    rowoff[1] = (size_t)h * DIM_W + w0;
    rowoff[2] = (size_t)(h + 1) * DIM_W + w0;

    float4 A0, B0, C0, A1, B1, C1, A2, B2, C2, cen1, cen2, dummy;
    float4 rc[3]; float rl[3], rr[3];

    // Prologue: partials for planes d0-1 (slot 1) and d0 (slot 2)
    load_raw(base, d0 - 1, (d0 - 1) >= 0, rowoff, hv, w0, rc, rl, rr);
    make_partials(rc, rl, rr, A1, B1, C1, dummy);
    load_raw(base, d0, true, rowoff, hv, w0, rc, rl, rr);
    make_partials(rc, rl, rr, A2, B2, C2, cen2);

#pragma unroll 1
    for (int dd = 0; dd <= DCHUNK; dd++) {
        const int p = d0 + dd + 1;
        const bool lv = (dd < DCHUNK) && (p < DIM_D);

        // (1) issue next-plane loads (consumed only at step 3)
        load_raw(base, p, lv, rowoff, hv, w0, rc, rl, rr);

        // (2) compute + store output plane d0+dd-1 from the register ring
        if (dd >= 1) {
            const int d = d0 + dd - 1;
            float4 gx, gy, gz, m;
            gx.x = B0.x + 2.f * B1.x + B2.x;
            gx.y = B0.y + 2.f * B1.y + B2.y;
            gx.z = B0.z + 2.f * B1.z + B2.z;
            gx.w = B0.w + 2.f * B1.w + B2.w;
            gy.x = C0.x + 2.f * C1.x + C2.x;
            gy.y = C0.y + 2.f * C1.y + C2.y;
            gy.z = C0.z + 2.f * C1.z + C2.z;
            gy.w = C0.w + 2.f * C1.w + C2.w;
            gz.x = A2.x - A0.x;
            gz.y = A2.y - A0.y;
            gz.z = A2.z - A0.z;
            gz.w = A2.w - A0.w;
            m.x = sqrtf(fmaf(gx.x, gx.x, fmaf(gy.x, gy.x, fmaf(gz.x, gz.x, 1e-8f))));
            m.y = sqrtf(fmaf(gx.y, gx.y, fmaf(gy.y, gy.y, fmaf(gz.y, gz.y, 1e-8f))));
            m.z = sqrtf(fmaf(gx.z, gx.z, fmaf(gy.z, gy.z, fmaf(gz.z, gz.z, 1e-8f))));
            m.w = sqrtf(fmaf(gx.w, gx.w, fmaf(gy.w, gy.w, fmaf(gz.w, gz.w, 1e-8f))));

            const size_t off = (size_t)d * PLANE;
            __stcs(reinterpret_cast<float4*>(o0 + off), cen1);  // copy channel
            __stcs(reinterpret_cast<float4*>(o1 + off), m);     // magnitude channel
        }

        // (3) rotate ring; fold the just-loaded plane into slot 2
        if (dd < DCHUNK) {
            A0 = A1; B0 = B1; C0 = C1;
            A1 = A2; B1 = B2; C1 = C2;
            cen1 = cen2;
            make_partials(rc, rl, rr, A2, B2, C2, cen2);
        }
    }
}

extern "C" void kernel_launch(void* const* d_in, const int* in_sizes, int n_in,
                              void* d_out, int out_size)
{
    const float* img = (const float*)d_in[0];
    float* out = (float*)d_out;

    dim3 block(64, 4, 1);                       // 256 threads
    dim3 grid(DIM_D / DCHUNK, DIM_H / 4, 4);    // 4 x 64 x 4 = 1024 CTAs

    sobel_edge_kernel<<<grid, block>>>(img, out);
}